// round 16
// baseline (speedup 1.0000x reference)
#include <cuda_runtime.h>
#include <cuda_bf16.h>
#include <cstdint>
#include <math.h>

// Problem constants
#define BB 8
#define SS 2048
#define DD 1024
#define MTOT (BB * SS)   // 16384

typedef __nv_bfloat16 bf16;

// Scratch (device globals; no allocation allowed)
__device__ float g_s[(size_t)BB * SS * SS];            // fp32 scores
__device__ bf16 g_inh[3 * (size_t)MTOT * DD], g_inl[3 * (size_t)MTOT * DD];
__device__ bf16 g_wh[4 * (size_t)DD * DD],  g_wl[4 * (size_t)DD * DD];
__device__ bf16 g_qkvh[3 * (size_t)MTOT * DD], g_qkvl[3 * (size_t)MTOT * DD];
__device__ bf16 g_ph[(size_t)BB * SS * SS], g_pl[(size_t)BB * SS * SS];
__device__ bf16 g_xh[(size_t)MTOT * DD], g_xl[(size_t)MTOT * DD];
__device__ float g_bias3[3 * DD];

// ---------------------------------------------------------------------------
// PTX helpers
// ---------------------------------------------------------------------------
__device__ __forceinline__ uint32_t smem_u32(const void* p) {
    uint32_t a;
    asm("{ .reg .u64 t; cvta.to.shared.u64 t, %1; cvt.u32.u64 %0, t; }"
        : "=r"(a) : "l"(p));
    return a;
}

#define CPA16(dst, src) \
    asm volatile("cp.async.cg.shared.global [%0], [%1], 16;" :: "r"(dst), "l"(src))
#define CP_COMMIT() asm volatile("cp.async.commit_group;" ::: "memory")
#define CP_WAIT0()  asm volatile("cp.async.wait_group 0;" ::: "memory")

#define LDSM4(r0, r1, r2, r3, addr) \
    asm volatile("ldmatrix.sync.aligned.m8n8.x4.shared.b16 {%0,%1,%2,%3}, [%4];" \
                 : "=r"(r0), "=r"(r1), "=r"(r2), "=r"(r3) : "r"(addr))

#define LDSM4T(r0, r1, r2, r3, addr) \
    asm volatile("ldmatrix.sync.aligned.m8n8.x4.trans.shared.b16 {%0,%1,%2,%3}, [%4];" \
                 : "=r"(r0), "=r"(r1), "=r"(r2), "=r"(r3) : "r"(addr))

#define MMA_BF16(d, a, b0, b1)                                              \
    asm volatile(                                                           \
        "mma.sync.aligned.m16n8k16.row.col.f32.bf16.bf16.f32 "              \
        "{%0,%1,%2,%3}, {%4,%5,%6,%7}, {%8,%9}, {%0,%1,%2,%3};"             \
        : "+f"((d)[0]), "+f"((d)[1]), "+f"((d)[2]), "+f"((d)[3])            \
        : "r"((a)[0]), "r"((a)[1]), "r"((a)[2]), "r"((a)[3]),               \
          "r"(b0), "r"(b1))

// fp32 -> bf16 hi/lo split
__device__ __forceinline__ void split1(float v, bf16& h, bf16& l) {
    h = __float2bfloat16_rn(v);
    l = __float2bfloat16_rn(v - __bfloat162float(h));
}

// SMEM geometry (bf16 tiles, BK=32, CTA tile 128x128) — champion geometry
#define A_STR   80       // 64B data + 16B pad per K-major row
#define BNN_STR 272      // 256B data + 16B pad per NN (n-major) row
#define TILE_A  10240    // 128 * 80
#define TILE_BNN 8704    // 32 * 272
#define STAGE_B 40960
#define SMEM_TOT (2 * STAGE_B)   // 81920 -> 2 CTAs/SM

// ---------------------------------------------------------------------------
// Split-bf16 tensor-core GEMM on pre-split operands, cp.async 2-stage,
// 2 CTAs/SM, ONE barrier per chunk. Term order: B_lo FIRST, so the long
// 32-MMA (B_hi) run lands last and covers the k16/chunk-boundary bubble.
//   C = A @ B' (+bias);  D = Ahi*Blo + Ahi*Bhi + Alo*Bhi
// CTA tile 128x128, BK=32, 256 threads (8 warps 2m x 4n), warp tile 64x32.
// ---------------------------------------------------------------------------
template <bool BT, bool BIAS, bool OUT_SPLIT>
__global__ __launch_bounds__(256, 2)
void tc_gemm(const bf16* __restrict__ Ah, const bf16* __restrict__ Al,
             const bf16* __restrict__ Bh, const bf16* __restrict__ Bl,
             const float* __restrict__ bias,
             float* __restrict__ C, bf16* __restrict__ Ch, bf16* __restrict__ Cl,
             int M, int N, int K,
             long sA, long sB, long sC, long sBias)
{
    extern __shared__ char smem[];
    const uint32_t sb = smem_u32(smem);
    const int tid = threadIdx.x;
    const int lane = tid & 31, wid = tid >> 5;
    const int bm = blockIdx.x * 128, bn = blockIdx.y * 128;
    const int wm = (wid & 1) * 64, wn = (wid >> 1) * 32;

    Ah += (long)blockIdx.z * sA;  Al += (long)blockIdx.z * sA;
    Bh += (long)blockIdx.z * sB;  Bl += (long)blockIdx.z * sB;
    if (BIAS) bias += (long)blockIdx.z * sBias;

    float acc[4][4][4];
#pragma unroll
    for (int i = 0; i < 4; i++)
#pragma unroll
        for (int j = 0; j < 4; j++)
#pragma unroll
            for (int r = 0; r < 4; r++) acc[i][j][r] = 0.f;

    const int arow = tid >> 2, acol = tid & 3;
    const int bkrow = tid >> 4, bkcol = tid & 15;

    auto issue_stage = [&](int slot, int ch) {
        const uint32_t st = sb + slot * STAGE_B;
        const int k0 = ch << 5;
        {
            long off = (long)(bm + arow) * K + k0 + acol * 8;
            long off2 = off + (long)64 * K;
            uint32_t d = st + arow * A_STR + acol * 16;
            uint32_t d2 = d + 64 * A_STR;
            CPA16(d, Ah + off);            CPA16(d + TILE_A, Al + off);
            CPA16(d2, Ah + off2);          CPA16(d2 + TILE_A, Al + off2);
        }
        if (BT) {
            long off = (long)(bn + arow) * K + k0 + acol * 8;
            long off2 = off + (long)64 * K;
            uint32_t d = st + 2 * TILE_A + arow * A_STR + acol * 16;
            uint32_t d2 = d + 64 * A_STR;
            CPA16(d, Bh + off);            CPA16(d + TILE_A, Bl + off);
            CPA16(d2, Bh + off2);          CPA16(d2 + TILE_A, Bl + off2);
        } else {
            long off = (long)(k0 + bkrow) * N + bn + bkcol * 8;
            long off2 = off + (long)16 * N;
            uint32_t d = st + 2 * TILE_A + bkrow * BNN_STR + bkcol * 16;
            uint32_t d2 = d + 16 * BNN_STR;
            CPA16(d, Bh + off);            CPA16(d + TILE_BNN, Bl + off);
            CPA16(d2, Bh + off2);          CPA16(d2 + TILE_BNN, Bl + off2);
        }
    };

    const int NCH = K >> 5;

    issue_stage(0, 0); CP_COMMIT();

    for (int ch = 0; ch < NCH; ch++) {
        const int buf = ch & 1;
        CP_WAIT0();          // only chunk ch outstanding -> chunk ch complete
        __syncthreads();     // data visible to all warps; prev-chunk reads done

        const uint32_t stg = sb + buf * STAGE_B;
        const uint32_t a_hi = stg, a_lo = stg + TILE_A;
        const uint32_t b_hi = stg + 2 * TILE_A;
        const uint32_t b_lo = b_hi + (BT ? TILE_A : TILE_BNN);

        bool first = true;
#pragma unroll
        for (int ks = 0; ks < 2; ks++) {
            const int k16 = ks * 16;
            uint32_t ah[4][4], al[4][4];
            {
                const int ar = wm + (lane & 15);
                const int ac = (k16 + (lane >> 4) * 8) * 2;
#pragma unroll
                for (int i = 0; i < 4; i++) {
                    uint32_t ad = a_hi + (ar + i * 16) * A_STR + ac;
                    LDSM4(ah[i][0], ah[i][1], ah[i][2], ah[i][3], ad);
                    uint32_t ad2 = a_lo + (ar + i * 16) * A_STR + ac;
                    LDSM4(al[i][0], al[i][1], al[i][2], al[i][3], ad2);
                }
            }
            uint32_t bb[2][4];
            // ---- B_lo FIRST: term Ahi*Blo (16 MMA) ----
            if (BT) {
                const int br = wn + (lane & 7) + (lane >> 4) * 8;
                const int bc = (k16 + ((lane >> 3) & 1) * 8) * 2;
#pragma unroll
                for (int j = 0; j < 2; j++) {
                    uint32_t bd = b_lo + (br + j * 16) * A_STR + bc;
                    LDSM4(bb[j][0], bb[j][1], bb[j][2], bb[j][3], bd);
                }
            } else {
                const int bk = k16 + (lane & 7) + ((lane >> 3) & 1) * 8;
                const int bcol = (wn + (lane >> 4) * 8) * 2;
#pragma unroll
                for (int j = 0; j < 2; j++) {
                    uint32_t bd = b_lo + bk * BNN_STR + bcol + j * 32;
                    LDSM4T(bb[j][0], bb[j][1], bb[j][2], bb[j][3], bd);
                }
            }
            // overlap next-chunk cp.async issue with this k16's MMAs
            if (first && ch + 1 < NCH) {
                issue_stage(buf ^ 1, ch + 1);
                CP_COMMIT();
            }
            first = false;
#pragma unroll
            for (int i = 0; i < 4; i++)
#pragma unroll
                for (int j = 0; j < 2; j++)
#pragma unroll
                    for (int h = 0; h < 2; h++)
                        MMA_BF16(acc[i][j * 2 + h], ah[i], bb[j][2 * h], bb[j][2 * h + 1]);
            // ---- B_hi LAST: terms Ahi*Bhi + Alo*Bhi (32 MMA tail) ----
            if (BT) {
                const int br = wn + (lane & 7) + (lane >> 4) * 8;
                const int bc = (k16 + ((lane >> 3) & 1) * 8) * 2;
#pragma unroll
                for (int j = 0; j < 2; j++) {
                    uint32_t bd = b_hi + (br + j * 16) * A_STR + bc;
                    LDSM4(bb[j][0], bb[j][1], bb[j][2], bb[j][3], bd);
                }
            } else {
                const int bk = k16 + (lane & 7) + ((lane >> 3) & 1) * 8;
                const int bcol = (wn + (lane >> 4) * 8) * 2;
#pragma unroll
                for (int j = 0; j < 2; j++) {
                    uint32_t bd = b_hi + bk * BNN_STR + bcol + j * 32;
                    LDSM4T(bb[j][0], bb[j][1], bb[j][2], bb[j][3], bd);
                }
            }
#pragma unroll
            for (int i = 0; i < 4; i++)
#pragma unroll
                for (int j = 0; j < 2; j++)
#pragma unroll
                    for (int h = 0; h < 2; h++) {
                        MMA_BF16(acc[i][j * 2 + h], ah[i], bb[j][2 * h], bb[j][2 * h + 1]);
                        MMA_BF16(acc[i][j * 2 + h], al[i], bb[j][2 * h], bb[j][2 * h + 1]);
                    }
        }
        // no trailing barrier: next iteration's post-wait barrier orders
        // this chunk's reads before the following issue into this slot.
    }

    // ---- epilogue ----
#pragma unroll
    for (int i = 0; i < 4; i++) {
        const int m0 = bm + wm + i * 16 + (lane >> 2);
#pragma unroll
        for (int jj = 0; jj < 4; jj++) {
            const int n0 = bn + wn + jj * 8 + (lane & 3) * 2;
            float v0 = acc[i][jj][0], v1 = acc[i][jj][1];
            float v2 = acc[i][jj][2], v3 = acc[i][jj][3];
            if (BIAS) {
                float bx = bias[n0], by = bias[n0 + 1];
                v0 += bx; v1 += by; v2 += bx; v3 += by;
            }
            if (OUT_SPLIT) {
                bf16 h0, l0, h1, l1;
                split1(v0, h0, l0); split1(v1, h1, l1);
                __nv_bfloat162 hh = {h0, h1}, ll = {l0, l1};
                long o = (long)blockIdx.z * sC + (long)m0 * N + n0;
                *(uint32_t*)(Ch + o) = *(uint32_t*)&hh;
                *(uint32_t*)(Cl + o) = *(uint32_t*)&ll;
                split1(v2, h0, l0); split1(v3, h1, l1);
                __nv_bfloat162 hh2 = {h0, h1}, ll2 = {l0, l1};
                long o2 = o + (long)8 * N;
                *(uint32_t*)(Ch + o2) = *(uint32_t*)&hh2;
                *(uint32_t*)(Cl + o2) = *(uint32_t*)&ll2;
            } else {
                long o = (long)blockIdx.z * sC + (long)m0 * N + n0;
                *(float2*)(C + o) = make_float2(v0, v1);
                *(float2*)(C + o + (long)8 * N) = make_float2(v2, v3);
            }
        }
    }
}

// ---------------------------------------------------------------------------
// Merged elementwise splits: 3 inputs (blockIdx.y selects tensor)
// ---------------------------------------------------------------------------
__global__ __launch_bounds__(256)
void split_in3(const float* __restrict__ a, const float* __restrict__ b,
               const float* __restrict__ c, bf16* __restrict__ hi,
               bf16* __restrict__ lo)
{
    const float* in = (blockIdx.y == 0) ? a : (blockIdx.y == 1) ? b : c;
    size_t base = (size_t)blockIdx.y * ((size_t)MTOT * DD / 4);
    size_t i = base + blockIdx.x * 256 + threadIdx.x;
    float4 v = ((const float4*)in)[blockIdx.x * 256 + threadIdx.x];
    bf16 h0, l0, h1, l1, h2, l2, h3, l3;
    split1(v.x, h0, l0); split1(v.y, h1, l1);
    split1(v.z, h2, l2); split1(v.w, h3, l3);
    __nv_bfloat162 ha = {h0, h1}, hb = {h2, h3};
    __nv_bfloat162 la = {l0, l1}, lb = {l2, l3};
    ((uint2*)hi)[i] = make_uint2(*(uint32_t*)&ha, *(uint32_t*)&hb);
    ((uint2*)lo)[i] = make_uint2(*(uint32_t*)&la, *(uint32_t*)&lb);
}

// Merged weight splits: 4 weights (blockIdx.y selects tensor)
__global__ __launch_bounds__(256)
void split_w4(const float* __restrict__ a, const float* __restrict__ b,
              const float* __restrict__ c, const float* __restrict__ d,
              bf16* __restrict__ hi, bf16* __restrict__ lo)
{
    const float* in = (blockIdx.y == 0) ? a : (blockIdx.y == 1) ? b
                    : (blockIdx.y == 2) ? c : d;
    size_t base = (size_t)blockIdx.y * ((size_t)DD * DD / 4);
    size_t i = base + blockIdx.x * 256 + threadIdx.x;
    float4 v = ((const float4*)in)[blockIdx.x * 256 + threadIdx.x];
    bf16 h0, l0, h1, l1, h2, l2, h3, l3;
    split1(v.x, h0, l0); split1(v.y, h1, l1);
    split1(v.z, h2, l2); split1(v.w, h3, l3);
    __nv_bfloat162 ha = {h0, h1}, hb = {h2, h3};
    __nv_bfloat162 la = {l0, l1}, lb = {l2, l3};
    ((uint2*)hi)[i] = make_uint2(*(uint32_t*)&ha, *(uint32_t*)&hb);
    ((uint2*)lo)[i] = make_uint2(*(uint32_t*)&la, *(uint32_t*)&lb);
}

// Gather q/k/v biases into one contiguous array
__global__ void copy_bias3(const float* __restrict__ a, const float* __restrict__ b,
                           const float* __restrict__ c, float* __restrict__ d)
{
    int i = blockIdx.x * 256 + threadIdx.x;
    if (i < DD) d[i] = a[i];
    else if (i < 2 * DD) d[i] = b[i - DD];
    else if (i < 3 * DD) d[i] = c[i - 2 * DD];
}

// ---------------------------------------------------------------------------
// Softmax: scale raw scores, softmax per row, write P as bf16 hi/lo.
// ---------------------------------------------------------------------------
__global__ __launch_bounds__(256)
void softmax_rows(const float* __restrict__ s, bf16* __restrict__ ph,
                  bf16* __restrict__ pl)
{
    const long row = blockIdx.x;
    const float* p = s + row * SS;
    const int tid = threadIdx.x;
    __shared__ float red[256];
    const float SCALE = 0.088388347648318447f;   // 1/sqrt(128)

    float4 v0 = ((const float4*)p)[tid * 2];
    float4 v1 = ((const float4*)p)[tid * 2 + 1];
    float e[8] = {v0.x * SCALE, v0.y * SCALE, v0.z * SCALE, v0.w * SCALE,
                  v1.x * SCALE, v1.y * SCALE, v1.z * SCALE, v1.w * SCALE};

    float mx = -1e30f;
#pragma unroll
    for (int i = 0; i < 8; i++) mx = fmaxf(mx, e[i]);
    red[tid] = mx;
    __syncthreads();
#pragma unroll
    for (int o = 128; o > 0; o >>= 1) {
        if (tid < o) red[tid] = fmaxf(red[tid], red[tid + o]);
        __syncthreads();
    }
    mx = red[0];
    __syncthreads();

    float sum = 0.f;
#pragma unroll
    for (int i = 0; i < 8; i++) { e[i] = __expf(e[i] - mx); sum += e[i]; }
    red[tid] = sum;
    __syncthreads();
#pragma unroll
    for (int o = 128; o > 0; o >>= 1) {
        if (tid < o) red[tid] += red[tid + o];
        __syncthreads();
    }
    const float inv = 1.f / red[0];

    bf16 h[8], l[8];
#pragma unroll
    for (int i = 0; i < 8; i++) split1(e[i] * inv, h[i], l[i]);
    ((uint4*)(ph + row * SS))[tid] = *(uint4*)h;
    ((uint4*)(pl + row * SS))[tid] = *(uint4*)l;
}

// ---------------------------------------------------------------------------
extern "C" void kernel_launch(void* const* d_in, const int* in_sizes, int n_in,
                              void* d_out, int out_size)
{
    const float* query = (const float*)d_in[0];
    const float* key   = (const float*)d_in[1];
    const float* value = (const float*)d_in[2];
    const float* Wq = (const float*)d_in[3];
    const float* bq = (const float*)d_in[4];
    const float* Wk = (const float*)d_in[5];
    const float* bk = (const float*)d_in[6];
    const float* Wv = (const float*)d_in[7];
    const float* bv = (const float*)d_in[8];
    const float* Wo = (const float*)d_in[9];
    const float* bo = (const float*)d_in[10];
    float* out = (float*)d_out;

    float *s, *bias3;
    bf16 *inh, *inl, *wh, *wl, *qkvh, *qkvl, *ph, *pl, *xh, *xl;
    cudaGetSymbolAddress((void**)&s, g_s);
    cudaGetSymbolAddress((void**)&inh, g_inh);   cudaGetSymbolAddress((void**)&inl, g_inl);
    cudaGetSymbolAddress((void**)&wh, g_wh);     cudaGetSymbolAddress((void**)&wl, g_wl);
    cudaGetSymbolAddress((void**)&qkvh, g_qkvh); cudaGetSymbolAddress((void**)&qkvl, g_qkvl);
    cudaGetSymbolAddress((void**)&ph, g_ph);     cudaGetSymbolAddress((void**)&pl, g_pl);
    cudaGetSymbolAddress((void**)&xh, g_xh);     cudaGetSymbolAddress((void**)&xl, g_xl);
    cudaGetSymbolAddress((void**)&bias3, g_bias3);

    static bool attr_done = false;
    if (!attr_done) {
        cudaFuncSetAttribute(tc_gemm<true, true, true>,
                             cudaFuncAttributeMaxDynamicSharedMemorySize, SMEM_TOT);
        cudaFuncSetAttribute(tc_gemm<true, false, false>,
                             cudaFuncAttributeMaxDynamicSharedMemorySize, SMEM_TOT);
        cudaFuncSetAttribute(tc_gemm<false, false, true>,
                             cudaFuncAttributeMaxDynamicSharedMemorySize, SMEM_TOT);
        cudaFuncSetAttribute(tc_gemm<true, true, false>,
                             cudaFuncAttributeMaxDynamicSharedMemorySize, SMEM_TOT);
        attr_done = true;
    }

    const dim3 blk(256);
    const size_t WD = (size_t)DD * DD;
    const size_t IN = (size_t)MTOT * DD;

    // ---- splits + bias gather (merged launches) ----
    dim3 gin(MTOT * DD / 1024, 3);
    split_in3<<<gin, blk>>>(query, key, value, inh, inl);
    dim3 gw(DD * DD / 1024, 4);
    split_w4<<<gw, blk>>>(Wq, Wk, Wv, Wo, wh, wl);
    copy_bias3<<<12, blk>>>(bq, bk, bv, bias3);

    // ---- merged QKV projections: one launch, z in [0,3) ----
    dim3 gp(MTOT / 128, DD / 128, 3);
    tc_gemm<true, true, true><<<gp, blk, SMEM_TOT>>>(
        inh, inl, wh, wl, bias3, nullptr, qkvh, qkvl, MTOT, DD, DD,
        (long)IN, (long)WD, (long)IN, (long)DD);

    // ---- scores: S = Q K^T (raw; scale folded into softmax) ----
    dim3 gs(SS / 128, SS / 128, BB);
    tc_gemm<true, false, false><<<gs, blk, SMEM_TOT>>>(
        qkvh, qkvl, qkvh + IN, qkvl + IN, nullptr, s, nullptr, nullptr,
        SS, SS, DD, (long)SS * DD, (long)SS * DD, (long)SS * SS, 0);

    // ---- softmax -> P (bf16 hi/lo) ----
    softmax_rows<<<BB * SS, blk>>>(s, ph, pl);

    // ---- X = P V (NN, split output) ----
    dim3 gx(SS / 128, DD / 128, BB);
    tc_gemm<false, false, true><<<gx, blk, SMEM_TOT>>>(
        ph, pl, qkvh + 2 * IN, qkvl + 2 * IN, nullptr, nullptr, xh, xl,
        SS, DD, SS, (long)SS * SS, (long)SS * DD, (long)SS * DD, 0);

    // ---- output projection -> fp32 out ----
    dim3 go(MTOT / 128, DD / 128, 1);
    tc_gemm<true, true, false><<<go, blk, SMEM_TOT>>>(
        xh, xl, wh + 3 * WD, wl + 3 * WD, bo, out, nullptr, nullptr,
        MTOT, DD, DD, 0, 0, 0, 0);
}

// round 17
// speedup vs baseline: 1.0339x; 1.0339x over previous
#include <cuda_runtime.h>
#include <cuda_bf16.h>
#include <cstdint>
#include <math.h>

// Problem constants
#define BB 8
#define SS 2048
#define DD 1024
#define MTOT (BB * SS)   // 16384

typedef __nv_bfloat16 bf16;

// Scratch (device globals; no allocation allowed)
__device__ float g_s[(size_t)BB * SS * SS];            // fp32 scores
__device__ bf16 g_inh[3 * (size_t)MTOT * DD], g_inl[3 * (size_t)MTOT * DD];
__device__ bf16 g_wh[4 * (size_t)DD * DD],  g_wl[4 * (size_t)DD * DD];
__device__ bf16 g_qkvh[3 * (size_t)MTOT * DD], g_qkvl[3 * (size_t)MTOT * DD];
__device__ bf16 g_ph[(size_t)BB * SS * SS], g_pl[(size_t)BB * SS * SS];
__device__ bf16 g_xh[(size_t)MTOT * DD], g_xl[(size_t)MTOT * DD];
__device__ float g_bias3[3 * DD];

// ---------------------------------------------------------------------------
// PTX helpers
// ---------------------------------------------------------------------------
__device__ __forceinline__ uint32_t smem_u32(const void* p) {
    uint32_t a;
    asm("{ .reg .u64 t; cvta.to.shared.u64 t, %1; cvt.u32.u64 %0, t; }"
        : "=r"(a) : "l"(p));
    return a;
}

#define CPA16(dst, src) \
    asm volatile("cp.async.cg.shared.global [%0], [%1], 16;" :: "r"(dst), "l"(src))
#define CP_COMMIT() asm volatile("cp.async.commit_group;" ::: "memory")
#define CP_WAIT0()  asm volatile("cp.async.wait_group 0;" ::: "memory")

#define LDSM4(r0, r1, r2, r3, addr) \
    asm volatile("ldmatrix.sync.aligned.m8n8.x4.shared.b16 {%0,%1,%2,%3}, [%4];" \
                 : "=r"(r0), "=r"(r1), "=r"(r2), "=r"(r3) : "r"(addr))

#define LDSM4T(r0, r1, r2, r3, addr) \
    asm volatile("ldmatrix.sync.aligned.m8n8.x4.trans.shared.b16 {%0,%1,%2,%3}, [%4];" \
                 : "=r"(r0), "=r"(r1), "=r"(r2), "=r"(r3) : "r"(addr))

#define MMA_BF16(d, a, b0, b1)                                              \
    asm volatile(                                                           \
        "mma.sync.aligned.m16n8k16.row.col.f32.bf16.bf16.f32 "              \
        "{%0,%1,%2,%3}, {%4,%5,%6,%7}, {%8,%9}, {%0,%1,%2,%3};"             \
        : "+f"((d)[0]), "+f"((d)[1]), "+f"((d)[2]), "+f"((d)[3])            \
        : "r"((a)[0]), "r"((a)[1]), "r"((a)[2]), "r"((a)[3]),               \
          "r"(b0), "r"(b1))

// fp32 -> bf16 hi/lo split
__device__ __forceinline__ void split1(float v, bf16& h, bf16& l) {
    h = __float2bfloat16_rn(v);
    l = __float2bfloat16_rn(v - __bfloat162float(h));
}

// SMEM geometry (bf16 tiles, BK=32, CTA tile 128x128) — champion geometry
#define A_STR   80       // 64B data + 16B pad per K-major row
#define BNN_STR 272      // 256B data + 16B pad per NN (n-major) row
#define TILE_A  10240    // 128 * 80
#define TILE_BNN 8704    // 32 * 272
#define STAGE_B 40960
#define SMEM_TOT (2 * STAGE_B)   // 81920 -> 2 CTAs/SM

// ---------------------------------------------------------------------------
// Split-bf16 tensor-core GEMM on pre-split operands, cp.async 2-stage,
// 2 CTAs/SM, ONE barrier per chunk (exact R15 champion loop):
//   C = A @ B' (+bias);  D = Ahi*Bhi + Alo*Bhi + Ahi*Blo
// CTA tile 128x128, BK=32, 256 threads (8 warps 2m x 4n), warp tile 64x32.
// ---------------------------------------------------------------------------
template <bool BT, bool BIAS, bool OUT_SPLIT>
__global__ __launch_bounds__(256, 2)
void tc_gemm(const bf16* __restrict__ Ah, const bf16* __restrict__ Al,
             const bf16* __restrict__ Bh, const bf16* __restrict__ Bl,
             const float* __restrict__ bias,
             float* __restrict__ C, bf16* __restrict__ Ch, bf16* __restrict__ Cl,
             int M, int N, int K,
             long sA, long sB, long sC, long sBias)
{
    extern __shared__ char smem[];
    const uint32_t sb = smem_u32(smem);
    const int tid = threadIdx.x;
    const int lane = tid & 31, wid = tid >> 5;
    const int bm = blockIdx.x * 128, bn = blockIdx.y * 128;
    const int wm = (wid & 1) * 64, wn = (wid >> 1) * 32;

    Ah += (long)blockIdx.z * sA;  Al += (long)blockIdx.z * sA;
    Bh += (long)blockIdx.z * sB;  Bl += (long)blockIdx.z * sB;
    if (BIAS) bias += (long)blockIdx.z * sBias;

    float acc[4][4][4];
#pragma unroll
    for (int i = 0; i < 4; i++)
#pragma unroll
        for (int j = 0; j < 4; j++)
#pragma unroll
            for (int r = 0; r < 4; r++) acc[i][j][r] = 0.f;

    const int arow = tid >> 2, acol = tid & 3;
    const int bkrow = tid >> 4, bkcol = tid & 15;

    auto issue_stage = [&](int slot, int ch) {
        const uint32_t st = sb + slot * STAGE_B;
        const int k0 = ch << 5;
        {
            long off = (long)(bm + arow) * K + k0 + acol * 8;
            long off2 = off + (long)64 * K;
            uint32_t d = st + arow * A_STR + acol * 16;
            uint32_t d2 = d + 64 * A_STR;
            CPA16(d, Ah + off);            CPA16(d + TILE_A, Al + off);
            CPA16(d2, Ah + off2);          CPA16(d2 + TILE_A, Al + off2);
        }
        if (BT) {
            long off = (long)(bn + arow) * K + k0 + acol * 8;
            long off2 = off + (long)64 * K;
            uint32_t d = st + 2 * TILE_A + arow * A_STR + acol * 16;
            uint32_t d2 = d + 64 * A_STR;
            CPA16(d, Bh + off);            CPA16(d + TILE_A, Bl + off);
            CPA16(d2, Bh + off2);          CPA16(d2 + TILE_A, Bl + off2);
        } else {
            long off = (long)(k0 + bkrow) * N + bn + bkcol * 8;
            long off2 = off + (long)16 * N;
            uint32_t d = st + 2 * TILE_A + bkrow * BNN_STR + bkcol * 16;
            uint32_t d2 = d + 16 * BNN_STR;
            CPA16(d, Bh + off);            CPA16(d + TILE_BNN, Bl + off);
            CPA16(d2, Bh + off2);          CPA16(d2 + TILE_BNN, Bl + off2);
        }
    };

    const int NCH = K >> 5;

    issue_stage(0, 0); CP_COMMIT();

    for (int ch = 0; ch < NCH; ch++) {
        const int buf = ch & 1;
        CP_WAIT0();          // only chunk ch outstanding -> chunk ch complete
        __syncthreads();     // data visible to all warps; prev-chunk reads done

        const uint32_t stg = sb + buf * STAGE_B;
        const uint32_t a_hi = stg, a_lo = stg + TILE_A;
        const uint32_t b_hi = stg + 2 * TILE_A;
        const uint32_t b_lo = b_hi + (BT ? TILE_A : TILE_BNN);

        bool first = true;
#pragma unroll
        for (int ks = 0; ks < 2; ks++) {
            const int k16 = ks * 16;
            uint32_t ah[4][4], al[4][4];
            {
                const int ar = wm + (lane & 15);
                const int ac = (k16 + (lane >> 4) * 8) * 2;
#pragma unroll
                for (int i = 0; i < 4; i++) {
                    uint32_t ad = a_hi + (ar + i * 16) * A_STR + ac;
                    LDSM4(ah[i][0], ah[i][1], ah[i][2], ah[i][3], ad);
                    uint32_t ad2 = a_lo + (ar + i * 16) * A_STR + ac;
                    LDSM4(al[i][0], al[i][1], al[i][2], al[i][3], ad2);
                }
            }
            uint32_t bb[2][4];
            // ---- B_hi: terms Ahi*Bhi and Alo*Bhi ----
            if (BT) {
                const int br = wn + (lane & 7) + (lane >> 4) * 8;
                const int bc = (k16 + ((lane >> 3) & 1) * 8) * 2;
#pragma unroll
                for (int j = 0; j < 2; j++) {
                    uint32_t bd = b_hi + (br + j * 16) * A_STR + bc;
                    LDSM4(bb[j][0], bb[j][1], bb[j][2], bb[j][3], bd);
                }
            } else {
                const int bk = k16 + (lane & 7) + ((lane >> 3) & 1) * 8;
                const int bcol = (wn + (lane >> 4) * 8) * 2;
#pragma unroll
                for (int j = 0; j < 2; j++) {
                    uint32_t bd = b_hi + bk * BNN_STR + bcol + j * 32;
                    LDSM4T(bb[j][0], bb[j][1], bb[j][2], bb[j][3], bd);
                }
            }
            // overlap next-chunk cp.async issue with this k16's MMAs
            if (first && ch + 1 < NCH) {
                issue_stage(buf ^ 1, ch + 1);
                CP_COMMIT();
            }
            first = false;
#pragma unroll
            for (int i = 0; i < 4; i++)
#pragma unroll
                for (int j = 0; j < 2; j++)
#pragma unroll
                    for (int h = 0; h < 2; h++) {
                        MMA_BF16(acc[i][j * 2 + h], ah[i], bb[j][2 * h], bb[j][2 * h + 1]);
                        MMA_BF16(acc[i][j * 2 + h], al[i], bb[j][2 * h], bb[j][2 * h + 1]);
                    }
            // ---- B_lo: term Ahi*Blo (reuse bb regs) ----
            if (BT) {
                const int br = wn + (lane & 7) + (lane >> 4) * 8;
                const int bc = (k16 + ((lane >> 3) & 1) * 8) * 2;
#pragma unroll
                for (int j = 0; j < 2; j++) {
                    uint32_t bd = b_lo + (br + j * 16) * A_STR + bc;
                    LDSM4(bb[j][0], bb[j][1], bb[j][2], bb[j][3], bd);
                }
            } else {
                const int bk = k16 + (lane & 7) + ((lane >> 3) & 1) * 8;
                const int bcol = (wn + (lane >> 4) * 8) * 2;
#pragma unroll
                for (int j = 0; j < 2; j++) {
                    uint32_t bd = b_lo + bk * BNN_STR + bcol + j * 32;
                    LDSM4T(bb[j][0], bb[j][1], bb[j][2], bb[j][3], bd);
                }
            }
#pragma unroll
            for (int i = 0; i < 4; i++)
#pragma unroll
                for (int j = 0; j < 2; j++)
#pragma unroll
                    for (int h = 0; h < 2; h++)
                        MMA_BF16(acc[i][j * 2 + h], ah[i], bb[j][2 * h], bb[j][2 * h + 1]);
        }
        // no trailing barrier: next iteration's post-wait barrier orders
        // this chunk's reads before the following issue into this slot.
    }

    // ---- epilogue ----
#pragma unroll
    for (int i = 0; i < 4; i++) {
        const int m0 = bm + wm + i * 16 + (lane >> 2);
#pragma unroll
        for (int jj = 0; jj < 4; jj++) {
            const int n0 = bn + wn + jj * 8 + (lane & 3) * 2;
            float v0 = acc[i][jj][0], v1 = acc[i][jj][1];
            float v2 = acc[i][jj][2], v3 = acc[i][jj][3];
            if (BIAS) {
                float bx = bias[n0], by = bias[n0 + 1];
                v0 += bx; v1 += by; v2 += bx; v3 += by;
            }
            if (OUT_SPLIT) {
                bf16 h0, l0, h1, l1;
                split1(v0, h0, l0); split1(v1, h1, l1);
                __nv_bfloat162 hh = {h0, h1}, ll = {l0, l1};
                long o = (long)blockIdx.z * sC + (long)m0 * N + n0;
                *(uint32_t*)(Ch + o) = *(uint32_t*)&hh;
                *(uint32_t*)(Cl + o) = *(uint32_t*)&ll;
                split1(v2, h0, l0); split1(v3, h1, l1);
                __nv_bfloat162 hh2 = {h0, h1}, ll2 = {l0, l1};
                long o2 = o + (long)8 * N;
                *(uint32_t*)(Ch + o2) = *(uint32_t*)&hh2;
                *(uint32_t*)(Cl + o2) = *(uint32_t*)&ll2;
            } else {
                long o = (long)blockIdx.z * sC + (long)m0 * N + n0;
                *(float2*)(C + o) = make_float2(v0, v1);
                *(float2*)(C + o + (long)8 * N) = make_float2(v2, v3);
            }
        }
    }
}

// ---------------------------------------------------------------------------
// Merged elementwise splits: 3 inputs (blockIdx.y selects tensor)
// ---------------------------------------------------------------------------
__global__ __launch_bounds__(256)
void split_in3(const float* __restrict__ a, const float* __restrict__ b,
               const float* __restrict__ c, bf16* __restrict__ hi,
               bf16* __restrict__ lo)
{
    const float* in = (blockIdx.y == 0) ? a : (blockIdx.y == 1) ? b : c;
    size_t base = (size_t)blockIdx.y * ((size_t)MTOT * DD / 4);
    size_t i = base + blockIdx.x * 256 + threadIdx.x;
    float4 v = ((const float4*)in)[blockIdx.x * 256 + threadIdx.x];
    bf16 h0, l0, h1, l1, h2, l2, h3, l3;
    split1(v.x, h0, l0); split1(v.y, h1, l1);
    split1(v.z, h2, l2); split1(v.w, h3, l3);
    __nv_bfloat162 ha = {h0, h1}, hb = {h2, h3};
    __nv_bfloat162 la = {l0, l1}, lb = {l2, l3};
    ((uint2*)hi)[i] = make_uint2(*(uint32_t*)&ha, *(uint32_t*)&hb);
    ((uint2*)lo)[i] = make_uint2(*(uint32_t*)&la, *(uint32_t*)&lb);
}

// Merged weight splits: 4 weights (blockIdx.y selects tensor)
__global__ __launch_bounds__(256)
void split_w4(const float* __restrict__ a, const float* __restrict__ b,
              const float* __restrict__ c, const float* __restrict__ d,
              bf16* __restrict__ hi, bf16* __restrict__ lo)
{
    const float* in = (blockIdx.y == 0) ? a : (blockIdx.y == 1) ? b
                    : (blockIdx.y == 2) ? c : d;
    size_t base = (size_t)blockIdx.y * ((size_t)DD * DD / 4);
    size_t i = base + blockIdx.x * 256 + threadIdx.x;
    float4 v = ((const float4*)in)[blockIdx.x * 256 + threadIdx.x];
    bf16 h0, l0, h1, l1, h2, l2, h3, l3;
    split1(v.x, h0, l0); split1(v.y, h1, l1);
    split1(v.z, h2, l2); split1(v.w, h3, l3);
    __nv_bfloat162 ha = {h0, h1}, hb = {h2, h3};
    __nv_bfloat162 la = {l0, l1}, lb = {l2, l3};
    ((uint2*)hi)[i] = make_uint2(*(uint32_t*)&ha, *(uint32_t*)&hb);
    ((uint2*)lo)[i] = make_uint2(*(uint32_t*)&la, *(uint32_t*)&lb);
}

// Gather q/k/v biases into one contiguous array
__global__ void copy_bias3(const float* __restrict__ a, const float* __restrict__ b,
                           const float* __restrict__ c, float* __restrict__ d)
{
    int i = blockIdx.x * 256 + threadIdx.x;
    if (i < DD) d[i] = a[i];
    else if (i < 2 * DD) d[i] = b[i - DD];
    else if (i < 3 * DD) d[i] = c[i - 2 * DD];
}

// ---------------------------------------------------------------------------
// Softmax: scale, softmax per row, write P as bf16 hi/lo.
// Warp-shuffle reductions: 2 barriers total (vs 16 in tree version).
// ---------------------------------------------------------------------------
__global__ __launch_bounds__(256)
void softmax_rows(const float* __restrict__ s, bf16* __restrict__ ph,
                  bf16* __restrict__ pl)
{
    const long row = blockIdx.x;
    const float* p = s + row * SS;
    const int tid = threadIdx.x;
    const int lane = tid & 31, wid = tid >> 5;
    __shared__ float red[16];    // [0..7] max partials, [8..15] sum partials
    const float SCALE = 0.088388347648318447f;   // 1/sqrt(128)

    float4 v0 = ((const float4*)p)[tid * 2];
    float4 v1 = ((const float4*)p)[tid * 2 + 1];
    float e[8] = {v0.x * SCALE, v0.y * SCALE, v0.z * SCALE, v0.w * SCALE,
                  v1.x * SCALE, v1.y * SCALE, v1.z * SCALE, v1.w * SCALE};

    // ---- max: warp shfl reduce, then 8 partials ----
    float mx = -1e30f;
#pragma unroll
    for (int i = 0; i < 8; i++) mx = fmaxf(mx, e[i]);
#pragma unroll
    for (int o = 16; o > 0; o >>= 1)
        mx = fmaxf(mx, __shfl_xor_sync(0xFFFFFFFFu, mx, o));
    if (lane == 0) red[wid] = mx;
    __syncthreads();
    float m0 = red[0];
#pragma unroll
    for (int w = 1; w < 8; w++) m0 = fmaxf(m0, red[w]);

    // ---- exp + sum: warp shfl reduce, then 8 partials ----
    float sum = 0.f;
#pragma unroll
    for (int i = 0; i < 8; i++) { e[i] = __expf(e[i] - m0); sum += e[i]; }
#pragma unroll
    for (int o = 16; o > 0; o >>= 1)
        sum += __shfl_xor_sync(0xFFFFFFFFu, sum, o);
    if (lane == 0) red[8 + wid] = sum;
    __syncthreads();
    float tot = red[8];
#pragma unroll
    for (int w = 1; w < 8; w++) tot += red[8 + w];
    const float inv = 1.f / tot;

    bf16 h[8], l[8];
#pragma unroll
    for (int i = 0; i < 8; i++) split1(e[i] * inv, h[i], l[i]);
    ((uint4*)(ph + row * SS))[tid] = *(uint4*)h;
    ((uint4*)(pl + row * SS))[tid] = *(uint4*)l;
}

// ---------------------------------------------------------------------------
extern "C" void kernel_launch(void* const* d_in, const int* in_sizes, int n_in,
                              void* d_out, int out_size)
{
    const float* query = (const float*)d_in[0];
    const float* key   = (const float*)d_in[1];
    const float* value = (const float*)d_in[2];
    const float* Wq = (const float*)d_in[3];
    const float* bq = (const float*)d_in[4];
    const float* Wk = (const float*)d_in[5];
    const float* bk = (const float*)d_in[6];
    const float* Wv = (const float*)d_in[7];
    const float* bv = (const float*)d_in[8];
    const float* Wo = (const float*)d_in[9];
    const float* bo = (const float*)d_in[10];
    float* out = (float*)d_out;

    float *s, *bias3;
    bf16 *inh, *inl, *wh, *wl, *qkvh, *qkvl, *ph, *pl, *xh, *xl;
    cudaGetSymbolAddress((void**)&s, g_s);
    cudaGetSymbolAddress((void**)&inh, g_inh);   cudaGetSymbolAddress((void**)&inl, g_inl);
    cudaGetSymbolAddress((void**)&wh, g_wh);     cudaGetSymbolAddress((void**)&wl, g_wl);
    cudaGetSymbolAddress((void**)&qkvh, g_qkvh); cudaGetSymbolAddress((void**)&qkvl, g_qkvl);
    cudaGetSymbolAddress((void**)&ph, g_ph);     cudaGetSymbolAddress((void**)&pl, g_pl);
    cudaGetSymbolAddress((void**)&xh, g_xh);     cudaGetSymbolAddress((void**)&xl, g_xl);
    cudaGetSymbolAddress((void**)&bias3, g_bias3);

    static bool attr_done = false;
    if (!attr_done) {
        cudaFuncSetAttribute(tc_gemm<true, true, true>,
                             cudaFuncAttributeMaxDynamicSharedMemorySize, SMEM_TOT);
        cudaFuncSetAttribute(tc_gemm<true, false, false>,
                             cudaFuncAttributeMaxDynamicSharedMemorySize, SMEM_TOT);
        cudaFuncSetAttribute(tc_gemm<false, false, true>,
                             cudaFuncAttributeMaxDynamicSharedMemorySize, SMEM_TOT);
        cudaFuncSetAttribute(tc_gemm<true, true, false>,
                             cudaFuncAttributeMaxDynamicSharedMemorySize, SMEM_TOT);
        attr_done = true;
    }

    const dim3 blk(256);
    const size_t WD = (size_t)DD * DD;
    const size_t IN = (size_t)MTOT * DD;

    // ---- splits + bias gather (merged launches) ----
    dim3 gin(MTOT * DD / 1024, 3);
    split_in3<<<gin, blk>>>(query, key, value, inh, inl);
    dim3 gw(DD * DD / 1024, 4);
    split_w4<<<gw, blk>>>(Wq, Wk, Wv, Wo, wh, wl);
    copy_bias3<<<12, blk>>>(bq, bk, bv, bias3);

    // ---- merged QKV projections: one launch, z in [0,3) ----
    dim3 gp(MTOT / 128, DD / 128, 3);
    tc_gemm<true, true, true><<<gp, blk, SMEM_TOT>>>(
        inh, inl, wh, wl, bias3, nullptr, qkvh, qkvl, MTOT, DD, DD,
        (long)IN, (long)WD, (long)IN, (long)DD);

    // ---- scores: S = Q K^T (raw; scale folded into softmax) ----
    dim3 gs(SS / 128, SS / 128, BB);
    tc_gemm<true, false, false><<<gs, blk, SMEM_TOT>>>(
        qkvh, qkvl, qkvh + IN, qkvl + IN, nullptr, s, nullptr, nullptr,
        SS, SS, DD, (long)SS * DD, (long)SS * DD, (long)SS * SS, 0);

    // ---- softmax -> P (bf16 hi/lo) ----
    softmax_rows<<<BB * SS, blk>>>(s, ph, pl);

    // ---- X = P V (NN, split output) ----
    dim3 gx(SS / 128, DD / 128, BB);
    tc_gemm<false, false, true><<<gx, blk, SMEM_TOT>>>(
        ph, pl, qkvh + 2 * IN, qkvl + 2 * IN, nullptr, nullptr, xh, xl,
        SS, DD, SS, (long)SS * SS, (long)SS * DD, (long)SS * DD, 0);

    // ---- output projection -> fp32 out ----
    dim3 go(MTOT / 128, DD / 128, 1);
    tc_gemm<true, true, false><<<go, blk, SMEM_TOT>>>(
        xh, xl, wh + 3 * WD, wl + 3 * WD, bo, out, nullptr, nullptr,
        MTOT, DD, DD, 0, 0, 0, 0);
}